// round 4
// baseline (speedup 1.0000x reference)
#include <cuda_runtime.h>
#include <cstdint>

#define N_DIM   512
#define K_DIM   32768
#define L_DIM   64
#define KTILE   128
#define NCHUNK  32
#define NCHUNKS (N_DIM / NCHUNK)     // 16
#define TOUT    1048608              // (32768-1)*32 + 64

#define CS_PITCH 132                 // conflict-free A-fragment reads (132 % 32 == 4)
#define FR_PITCH 66
#define SMEM_FLOATS 8448             // max(32*132=4224 tile, 128*66=8448 epilogue)

// V pre-formatted as tf32 B-fragments: [cc(16)][s(4)][bt(8)][lane(32)] float2
__device__ float2 g_vf[16 * 4 * 8 * 32];

static __device__ __forceinline__ uint32_t f2tf32(float f) {
    uint32_t u;
    asm("cvt.rna.tf32.f32 %0, %1;" : "=r"(u) : "f"(f));
    return u;
}

static __device__ __forceinline__ void mma_tf32(float d[4], const uint32_t a[4],
                                                const uint32_t b[2]) {
    asm volatile(
        "mma.sync.aligned.m16n8k8.row.col.f32.tf32.tf32.f32 "
        "{%0,%1,%2,%3}, {%4,%5,%6,%7}, {%8,%9}, {%0,%1,%2,%3};"
        : "+f"(d[0]), "+f"(d[1]), "+f"(d[2]), "+f"(d[3])
        : "r"(a[0]), "r"(a[1]), "r"(a[2]), "r"(a[3]), "r"(b[0]), "r"(b[1]));
}

// ---- one-time V fragment prep: b0 = V[l][n], b1 = V[l][n+4] (tf32 bits) ----
__global__ void vf_kernel(const float* __restrict__ V) {
    const int idx  = blockIdx.x * blockDim.x + threadIdx.x;   // 0..16383
    const int lane = idx & 31;
    const int bt   = (idx >> 5) & 7;
    const int s    = (idx >> 8) & 3;
    const int cc   = idx >> 10;
    const int grp  = lane >> 2, qid = lane & 3;
    const int l = bt * 8 + grp;
    const int n = cc * NCHUNK + s * 8 + qid;
    float2 v;
    v.x = __uint_as_float(f2tf32(V[l * N_DIM + n]));
    v.y = __uint_as_float(f2tf32(V[l * N_DIM + n + 4]));
    g_vf[idx] = v;
}

// ---- zero only boundary tiles (32 samples at each 128-frame seam) ----
__global__ void zero_bounds(float* __restrict__ y) {
    const int i = blockIdx.x * blockDim.x + threadIdx.x;      // 8 * 257 * 32
    if (i >= 8 * 257 * 32) return;
    const int b = i / (257 * 32);
    const int r = i % (257 * 32);
    const int t = r >> 5, j = r & 31;
    y[(size_t)b * TOUT + (size_t)t * 4096 + j] = 0.f;
}

// ---- main: CTA = (b, 128 frames), 4 warps, warp tile m32 x n64 ----
__global__ void __launch_bounds__(128)
decoder_kernel(const float* __restrict__ c, float* __restrict__ y) {
    __shared__ __align__(16) float sm[SMEM_FLOATS];

    const int tid  = threadIdx.x;
    const int wid  = tid >> 5;
    const int lane = tid & 31;
    const int grp  = lane >> 2;
    const int qid  = lane & 3;
    const int k0   = blockIdx.x * KTILE;
    const int b    = blockIdx.y;
    const int wm   = wid * 32;

    const float* cb = c + ((size_t)b * N_DIM) * K_DIM + k0;

    float acc[2][8][4];
    #pragma unroll
    for (int mt = 0; mt < 2; ++mt)
        #pragma unroll
        for (int bt = 0; bt < 8; ++bt)
            #pragma unroll
            for (int r = 0; r < 4; ++r) acc[mt][bt][r] = 0.f;

    uint32_t creg[32];

    // ---- stage chunk 0: c[b, 0:32, k0:k0+128] -> cs (tf32) ----
    #pragma unroll
    for (int it = 0; it < 8; ++it) {
        const int idx = it * 128 + tid;
        const int n = idx >> 5, q = idx & 31;
        float4 v = *reinterpret_cast<const float4*>(cb + (size_t)n * K_DIM + 4 * q);
        creg[it*4+0] = f2tf32(v.x); creg[it*4+1] = f2tf32(v.y);
        creg[it*4+2] = f2tf32(v.z); creg[it*4+3] = f2tf32(v.w);
    }
    #pragma unroll
    for (int it = 0; it < 8; ++it) {
        const int idx = it * 128 + tid;
        const int n = idx >> 5, q = idx & 31;
        *reinterpret_cast<uint4*>(sm + n * CS_PITCH + 4 * q) =
            make_uint4(creg[it*4+0], creg[it*4+1], creg[it*4+2], creg[it*4+3]);
    }
    __syncthreads();

    #pragma unroll 1
    for (int cc = 0; cc < NCHUNKS; ++cc) {
        // prefetch next c chunk into registers (hidden behind MMAs)
        if (cc + 1 < NCHUNKS) {
            const int n0 = (cc + 1) * NCHUNK;
            #pragma unroll
            for (int it = 0; it < 8; ++it) {
                const int idx = it * 128 + tid;
                const int n = idx >> 5, q = idx & 31;
                float4 v = *reinterpret_cast<const float4*>(
                    cb + (size_t)(n0 + n) * K_DIM + 4 * q);
                creg[it*4+0] = f2tf32(v.x); creg[it*4+1] = f2tf32(v.y);
                creg[it*4+2] = f2tf32(v.z); creg[it*4+3] = f2tf32(v.w);
            }
        }

        // compute: 4 s-steps of kred=8
        #pragma unroll
        for (int s = 0; s < 4; ++s) {
            // B fragments straight from prepped global (L1-hot, coalesced 256B)
            const float2* vf = g_vf + ((size_t)(cc * 4 + s) * 8) * 32 + lane;
            uint32_t bf[8][2];
            #pragma unroll
            for (int bt = 0; bt < 8; ++bt) {
                float2 bv = vf[bt * 32];
                bf[bt][0] = __float_as_uint(bv.x);
                bf[bt][1] = __float_as_uint(bv.y);
            }
            // A fragments from SMEM (conflict-free, read exactly once per element)
            const uint32_t* ar0 = reinterpret_cast<const uint32_t*>(
                sm + (8 * s + qid) * CS_PITCH + wm + grp);
            const uint32_t* ar1 = reinterpret_cast<const uint32_t*>(
                sm + (8 * s + qid + 4) * CS_PITCH + wm + grp);
            uint32_t a[2][4];
            #pragma unroll
            for (int mt = 0; mt < 2; ++mt) {
                a[mt][0] = ar0[mt * 16];
                a[mt][1] = ar0[mt * 16 + 8];
                a[mt][2] = ar1[mt * 16];
                a[mt][3] = ar1[mt * 16 + 8];
            }
            #pragma unroll
            for (int mt = 0; mt < 2; ++mt)
                #pragma unroll
                for (int bt = 0; bt < 8; ++bt)
                    mma_tf32(acc[mt][bt], a[mt], bf[bt]);
        }
        __syncthreads();

        if (cc + 1 < NCHUNKS) {
            #pragma unroll
            for (int it = 0; it < 8; ++it) {
                const int idx = it * 128 + tid;
                const int n = idx >> 5, q = idx & 31;
                *reinterpret_cast<uint4*>(sm + n * CS_PITCH + 4 * q) =
                    make_uint4(creg[it*4+0], creg[it*4+1], creg[it*4+2], creg[it*4+3]);
            }
        }
        __syncthreads();
    }

    // ---- epilogue: stage frames, overlap-add ----
    float* fr = sm;   // 128 x FR_PITCH
    #pragma unroll
    for (int mt = 0; mt < 2; ++mt) {
        #pragma unroll
        for (int bt = 0; bt < 8; ++bt) {
            const int row = wm + mt * 16 + grp;
            const int col = bt * 8 + 2 * qid;
            *reinterpret_cast<float2*>(fr + row * FR_PITCH + col) =
                make_float2(acc[mt][bt][0], acc[mt][bt][1]);
            *reinterpret_cast<float2*>(fr + (row + 8) * FR_PITCH + col) =
                make_float2(acc[mt][bt][2], acc[mt][bt][3]);
        }
    }
    __syncthreads();

    float* yb = y + (size_t)b * TOUT;
    const int k = tid;   // 128 threads = 128 frames
    if (k == 0) {
        #pragma unroll
        for (int j = 0; j < 32; ++j)
            atomicAdd(&yb[(size_t)32 * k0 + j], fr[j]);
    } else {
        const float* f0 = fr + k * FR_PITCH;
        const float* f1 = fr + (k - 1) * FR_PITCH + 32;
        float4* o = reinterpret_cast<float4*>(yb + (size_t)32 * (k0 + k));
        #pragma unroll
        for (int q = 0; q < 8; ++q)
            o[q] = make_float4(f0[4*q+0] + f1[4*q+0], f0[4*q+1] + f1[4*q+1],
                               f0[4*q+2] + f1[4*q+2], f0[4*q+3] + f1[4*q+3]);
    }
    if (k == 127) {
        const float* f1 = fr + 127 * FR_PITCH + 32;
        #pragma unroll
        for (int j = 0; j < 32; ++j)
            atomicAdd(&yb[(size_t)32 * (k0 + KTILE) + j], f1[j]);
    }
}

extern "C" void kernel_launch(void* const* d_in, const int* in_sizes, int n_in,
                              void* d_out, int out_size) {
    const float* c = (const float*)d_in[0];
    const float* V = (const float*)d_in[1];
    if (in_sizes[0] == L_DIM * N_DIM) { c = (const float*)d_in[1]; V = (const float*)d_in[0]; }
    float* y = (float*)d_out;

    vf_kernel<<<64, 256>>>(V);                       // 16384 fragment pairs
    zero_bounds<<<(8 * 257 * 32 + 255) / 256, 256>>>(y);

    dim3 grid(K_DIM / KTILE, 8);                     // (256, 8)
    decoder_kernel<<<grid, 128>>>(c, y);
}